// round 3
// baseline (speedup 1.0000x reference)
#include <cuda_runtime.h>
#include <math.h>

#define NN 50000
#define NE 800000
#define DD 128
#define ED 16
#define SCAN_NBLK ((NN + 1023) / 1024)   // 49

// Scratch (allocation-free rule: __device__ globals)
__device__ float g_bufA[NN * DD];
__device__ float g_bufB[NN * DD];
__device__ int   g_idx64;
__device__ int   g_cnt[NN];
__device__ int   g_rowptr[NN + 1];
__device__ int   g_cursor[NN];
__device__ int   g_blocksum[SCAN_NBLK];
__device__ int   g_blockoff[SCAN_NBLK];
__device__ int2  g_edges[NE];   // {src, edge_id} sorted by dst

// ---------------------------------------------------------------------------
// Detect int64 vs int32 edge_idx
// ---------------------------------------------------------------------------
__global__ void detect_idx_kernel(const long long* __restrict__ idx) {
    if (threadIdx.x == 0 && blockIdx.x == 0) {
        int ok = 1;
        #pragma unroll 1
        for (int i = 0; i < 64; i++) {
            long long v = idx[i];
            if (v < 0 || v >= (long long)NN) { ok = 0; break; }
        }
        g_idx64 = ok;
    }
}

// ---------------------------------------------------------------------------
// CSR build
// ---------------------------------------------------------------------------
__global__ void zero_cnt_kernel() {
    int i = blockIdx.x * blockDim.x + threadIdx.x;
    if (i < NN) g_cnt[i] = 0;
}

__global__ void hist_kernel(const void* __restrict__ edge_idx) {
    int e = blockIdx.x * blockDim.x + threadIdx.x;
    if (e >= NE) return;
    int dst;
    if (g_idx64) dst = (int)((const long long*)edge_idx)[NE + e];
    else         dst = ((const int*)edge_idx)[NE + e];
    atomicAdd(&g_cnt[dst], 1);
}

// Per-block exclusive scan of 1024 elements; emits block totals.
__global__ void local_scan_kernel() {
    __shared__ int sdata[1024];
    int i = blockIdx.x * 1024 + threadIdx.x;
    int v = (i < NN) ? g_cnt[i] : 0;
    sdata[threadIdx.x] = v;
    __syncthreads();
    #pragma unroll
    for (int off = 1; off < 1024; off <<= 1) {
        int t = (threadIdx.x >= off) ? sdata[threadIdx.x - off] : 0;
        __syncthreads();
        sdata[threadIdx.x] += t;
        __syncthreads();
    }
    if (i < NN) g_rowptr[i] = sdata[threadIdx.x] - v;   // local exclusive
    if (threadIdx.x == 1023) g_blocksum[blockIdx.x] = sdata[1023];
}

__global__ void scan_sums_kernel() {
    if (threadIdx.x == 0) {
        int run = 0;
        #pragma unroll 1
        for (int b = 0; b < SCAN_NBLK; b++) {
            g_blockoff[b] = run;
            run += g_blocksum[b];
        }
    }
}

__global__ void add_off_kernel() {
    int i = blockIdx.x * 1024 + threadIdx.x;
    if (i < NN) {
        int v = g_rowptr[i] + g_blockoff[blockIdx.x];
        g_rowptr[i] = v;
        g_cursor[i] = v;
    }
    if (i == 0) g_rowptr[NN] = NE;   // total edges is known
}

__global__ void scatter_kernel(const void* __restrict__ edge_idx) {
    int e = blockIdx.x * blockDim.x + threadIdx.x;
    if (e >= NE) return;
    int src, dst;
    if (g_idx64) {
        src = (int)((const long long*)edge_idx)[e];
        dst = (int)((const long long*)edge_idx)[NE + e];
    } else {
        src = ((const int*)edge_idx)[e];
        dst = ((const int*)edge_idx)[NE + e];
    }
    int pos = atomicAdd(&g_cursor[dst], 1);
    g_edges[pos] = make_int2(src, e);
}

// ---------------------------------------------------------------------------
// Edge aggregation (CSR, no atomics): one warp per dst node, software-
// pipelined inner loop (prefetch next edge's idx/attr/x while doing FMAs).
// ---------------------------------------------------------------------------
__global__ void __launch_bounds__(256)
aggr_kernel(const float* __restrict__ xin,
            const float* __restrict__ edge_attr,
            const float* __restrict__ We,
            const float* __restrict__ be,
            const float* __restrict__ eps, int l,
            float* __restrict__ aggr) {
    int lane = threadIdx.x & 31;
    int warp = (blockIdx.x * blockDim.x + threadIdx.x) >> 5;
    int nwarps = (gridDim.x * blockDim.x) >> 5;
    int c0 = lane * 4;

    float4 w[ED];
    #pragma unroll
    for (int k = 0; k < ED; k++)
        w[k] = *(const float4*)(We + k * DD + c0);
    float4 bias = *(const float4*)(be + c0);
    float s = 1.0f + eps[l];

    for (int d = warp; d < NN; d += nwarps) {
        float4 xv = *(const float4*)(xin + (size_t)d * DD + c0);
        float4 acc = make_float4(xv.x * s, xv.y * s, xv.z * s, xv.w * s);
        int beg = g_rowptr[d], end = g_rowptr[d + 1];

        if (beg < end) {
            // prologue: load first edge
            int2 ed = g_edges[beg];
            const float4* ea4 = (const float4*)(edge_attr + (size_t)ed.y * ED);
            float4 t0 = ea4[0], t1 = ea4[1], t2 = ea4[2], t3 = ea4[3];
            float4 xs = *(const float4*)(xin + (size_t)ed.x * DD + c0);

            for (int j = beg; j < end; j++) {
                // prefetch next edge before the FMA chain
                int2 edn; float4 n0, n1, n2, n3, xsn;
                if (j + 1 < end) {
                    edn = g_edges[j + 1];
                    const float4* nea = (const float4*)(edge_attr + (size_t)edn.y * ED);
                    n0 = nea[0]; n1 = nea[1]; n2 = nea[2]; n3 = nea[3];
                    xsn = *(const float4*)(xin + (size_t)edn.x * DD + c0);
                }

                float4 m = bias;
                m.x += t0.x*w[0].x;  m.y += t0.x*w[0].y;  m.z += t0.x*w[0].z;  m.w += t0.x*w[0].w;
                m.x += t0.y*w[1].x;  m.y += t0.y*w[1].y;  m.z += t0.y*w[1].z;  m.w += t0.y*w[1].w;
                m.x += t0.z*w[2].x;  m.y += t0.z*w[2].y;  m.z += t0.z*w[2].z;  m.w += t0.z*w[2].w;
                m.x += t0.w*w[3].x;  m.y += t0.w*w[3].y;  m.z += t0.w*w[3].z;  m.w += t0.w*w[3].w;
                m.x += t1.x*w[4].x;  m.y += t1.x*w[4].y;  m.z += t1.x*w[4].z;  m.w += t1.x*w[4].w;
                m.x += t1.y*w[5].x;  m.y += t1.y*w[5].y;  m.z += t1.y*w[5].z;  m.w += t1.y*w[5].w;
                m.x += t1.z*w[6].x;  m.y += t1.z*w[6].y;  m.z += t1.z*w[6].z;  m.w += t1.z*w[6].w;
                m.x += t1.w*w[7].x;  m.y += t1.w*w[7].y;  m.z += t1.w*w[7].z;  m.w += t1.w*w[7].w;
                m.x += t2.x*w[8].x;  m.y += t2.x*w[8].y;  m.z += t2.x*w[8].z;  m.w += t2.x*w[8].w;
                m.x += t2.y*w[9].x;  m.y += t2.y*w[9].y;  m.z += t2.y*w[9].z;  m.w += t2.y*w[9].w;
                m.x += t2.z*w[10].x; m.y += t2.z*w[10].y; m.z += t2.z*w[10].z; m.w += t2.z*w[10].w;
                m.x += t2.w*w[11].x; m.y += t2.w*w[11].y; m.z += t2.w*w[11].z; m.w += t2.w*w[11].w;
                m.x += t3.x*w[12].x; m.y += t3.x*w[12].y; m.z += t3.x*w[12].z; m.w += t3.x*w[12].w;
                m.x += t3.y*w[13].x; m.y += t3.y*w[13].y; m.z += t3.y*w[13].z; m.w += t3.y*w[13].w;
                m.x += t3.z*w[14].x; m.y += t3.z*w[14].y; m.z += t3.z*w[14].z; m.w += t3.z*w[14].w;
                m.x += t3.w*w[15].x; m.y += t3.w*w[15].y; m.z += t3.w*w[15].z; m.w += t3.w*w[15].w;

                acc.x += fmaxf(m.x + xs.x, 0.0f);
                acc.y += fmaxf(m.y + xs.y, 0.0f);
                acc.z += fmaxf(m.z + xs.z, 0.0f);
                acc.w += fmaxf(m.w + xs.w, 0.0f);

                t0 = n0; t1 = n1; t2 = n2; t3 = n3; xs = xsn;
            }
        }
        *(float4*)(aggr + (size_t)d * DD + c0) = acc;
    }
}

// ---------------------------------------------------------------------------
// Fused node MLP, 64-row tiles, single weight buffer (W1 then W2) -> ~99KB
// smem -> 2 blocks/SM. C = gelu_exact(A @ W1 + b1) @ W2 + b2.
// ---------------------------------------------------------------------------
#define SA_PITCH 132
#define MLP_ROWS 64
#define MLP_SMEM_FLOATS (MLP_ROWS * SA_PITCH + 128 * 128 + 256)
#define MLP_SMEM_BYTES (MLP_SMEM_FLOATS * 4)

__global__ void __launch_bounds__(256, 2)
mlp_kernel(const float* __restrict__ A,
           const float* __restrict__ W1g,
           const float* __restrict__ b1g,
           const float* __restrict__ W2g,
           const float* __restrict__ b2g,
           float* __restrict__ C) {
    extern __shared__ float sm[];
    float* sA = sm;                        // 64 x 132 (padded)
    float* sW = sm + MLP_ROWS * SA_PITCH;  // 128 x 128 (W1 then W2)
    float* sb1 = sW + 128 * 128;           // 128
    float* sb2 = sb1 + 128;                // 128

    int tid = threadIdx.x;
    int row0 = blockIdx.x * MLP_ROWS;

    // load W1 + biases + A tile
    for (int i = tid; i < 128 * 32; i += 256)
        ((float4*)sW)[i] = ((const float4*)W1g)[i];
    if (tid < 128) { sb1[tid] = b1g[tid]; sb2[tid] = b2g[tid]; }
    for (int i = tid; i < MLP_ROWS * 32; i += 256) {
        int r = i >> 5, k4 = i & 31;
        int gr = row0 + r;
        float4 v = (gr < NN) ? ((const float4*)(A + (size_t)gr * DD))[k4]
                             : make_float4(0.f, 0.f, 0.f, 0.f);
        *(float4*)(sA + r * SA_PITCH + k4 * 4) = v;
    }
    __syncthreads();

    int tx = tid & 15, ty = tid >> 4;     // 16 col-groups x 16 row-groups
    int r0 = ty * 4, cc = tx * 8;         // 4 rows x 8 cols per thread

    float acc[4][8];
    #pragma unroll
    for (int i = 0; i < 4; i++)
        #pragma unroll
        for (int j = 0; j < 8; j++) acc[i][j] = 0.0f;

    // GEMM1: acc = A @ W1
    #pragma unroll 4
    for (int k = 0; k < 128; k++) {
        float4 wa = *(const float4*)(sW + k * 128 + cc);
        float4 wb = *(const float4*)(sW + k * 128 + cc + 4);
        float a[4];
        #pragma unroll
        for (int i = 0; i < 4; i++) a[i] = sA[(r0 + i) * SA_PITCH + k];
        #pragma unroll
        for (int i = 0; i < 4; i++) {
            acc[i][0] += a[i] * wa.x; acc[i][1] += a[i] * wa.y;
            acc[i][2] += a[i] * wa.z; acc[i][3] += a[i] * wa.w;
            acc[i][4] += a[i] * wb.x; acc[i][5] += a[i] * wb.y;
            acc[i][6] += a[i] * wb.z; acc[i][7] += a[i] * wb.w;
        }
    }
    __syncthreads();   // done reading sA and sW

    // H = gelu(acc + b1) -> sA ; load W2 -> sW
    #pragma unroll
    for (int i = 0; i < 4; i++) {
        #pragma unroll
        for (int j = 0; j < 8; j++) {
            float h = acc[i][j] + sb1[cc + j];
            h = 0.5f * h * (1.0f + erff(h * 0.70710678118654752f));
            sA[(r0 + i) * SA_PITCH + cc + j] = h;
            acc[i][j] = 0.0f;
        }
    }
    for (int i = tid; i < 128 * 32; i += 256)
        ((float4*)sW)[i] = ((const float4*)W2g)[i];
    __syncthreads();

    // GEMM2: acc = H @ W2
    #pragma unroll 4
    for (int k = 0; k < 128; k++) {
        float4 wa = *(const float4*)(sW + k * 128 + cc);
        float4 wb = *(const float4*)(sW + k * 128 + cc + 4);
        float a[4];
        #pragma unroll
        for (int i = 0; i < 4; i++) a[i] = sA[(r0 + i) * SA_PITCH + k];
        #pragma unroll
        for (int i = 0; i < 4; i++) {
            acc[i][0] += a[i] * wa.x; acc[i][1] += a[i] * wa.y;
            acc[i][2] += a[i] * wa.z; acc[i][3] += a[i] * wa.w;
            acc[i][4] += a[i] * wb.x; acc[i][5] += a[i] * wb.y;
            acc[i][6] += a[i] * wb.z; acc[i][7] += a[i] * wb.w;
        }
    }

    #pragma unroll
    for (int i = 0; i < 4; i++) {
        int gr = row0 + r0 + i;
        if (gr < NN) {
            float4 o0 = make_float4(acc[i][0] + sb2[cc],     acc[i][1] + sb2[cc + 1],
                                    acc[i][2] + sb2[cc + 2], acc[i][3] + sb2[cc + 3]);
            float4 o1 = make_float4(acc[i][4] + sb2[cc + 4], acc[i][5] + sb2[cc + 5],
                                    acc[i][6] + sb2[cc + 6], acc[i][7] + sb2[cc + 7]);
            *(float4*)(C + (size_t)gr * DD + cc) = o0;
            *(float4*)(C + (size_t)gr * DD + cc + 4) = o1;
        }
    }
}

// ---------------------------------------------------------------------------
// Launch
// ---------------------------------------------------------------------------
extern "C" void kernel_launch(void* const* d_in, const int* in_sizes, int n_in,
                              void* d_out, int out_size) {
    const float* x         = (const float*)d_in[0];
    const float* edge_attr = (const float*)d_in[1];
    const float* W1        = (const float*)d_in[2];
    const float* b1        = (const float*)d_in[3];
    const float* W2        = (const float*)d_in[4];
    const float* b2        = (const float*)d_in[5];
    const float* We        = (const float*)d_in[6];
    const float* be        = (const float*)d_in[7];
    const float* eps       = (const float*)d_in[8];
    const void*  edge_idx  = d_in[9];
    float* out = (float*)d_out;

    float *bufA, *bufB;
    cudaGetSymbolAddress((void**)&bufA, g_bufA);
    cudaGetSymbolAddress((void**)&bufB, g_bufB);

    cudaFuncSetAttribute(mlp_kernel,
                         cudaFuncAttributeMaxDynamicSharedMemorySize,
                         MLP_SMEM_BYTES);

    // ---- CSR build (once per launch) ----
    detect_idx_kernel<<<1, 32>>>((const long long*)edge_idx);
    zero_cnt_kernel<<<(NN + 255) / 256, 256>>>();
    hist_kernel<<<(NE + 255) / 256, 256>>>(edge_idx);
    local_scan_kernel<<<SCAN_NBLK, 1024>>>();
    scan_sums_kernel<<<1, 32>>>();
    add_off_kernel<<<SCAN_NBLK, 1024>>>();
    scatter_kernel<<<(NE + 255) / 256, 256>>>(edge_idx);

    const int aggr_blocks = (NN * 32 + 255) / 256;       // one warp per node
    const int mlp_blocks  = (NN + MLP_ROWS - 1) / MLP_ROWS;

    const float* xin = x;
    for (int l = 0; l < 3; l++) {
        float* aggr = (l == 1) ? bufB : bufA;
        float* xout = (l == 0) ? bufA : ((l == 1) ? bufB : out);

        aggr_kernel<<<aggr_blocks, 256>>>(xin, edge_attr, We + l * ED * DD,
                                          be + l * DD, eps, l, aggr);
        mlp_kernel<<<mlp_blocks, 256, MLP_SMEM_BYTES>>>(
            aggr, W1 + l * DD * DD, b1 + l * DD,
            W2 + l * DD * DD, b2 + l * DD, xout);
        xin = xout;
    }
}

// round 4
// speedup vs baseline: 1.3202x; 1.3202x over previous
#include <cuda_runtime.h>
#include <math.h>

#define NN 50000
#define NE 800000
#define DD 128
#define ED 16
#define SCAN_NBLK ((NN + 1023) / 1024)   // 49

// Scratch (allocation-free rule: __device__ globals)
__device__ float g_bufA[NN * DD];
__device__ float g_bufB[NN * DD];
__device__ int   g_idx64;
__device__ int   g_cnt[NN];
__device__ int   g_rowptr[NN + 1];
__device__ int   g_cursor[NN];
__device__ int   g_blocksum[SCAN_NBLK];
__device__ int   g_blockoff[SCAN_NBLK];
__device__ int   g_src[NE];              // src node, dst-sorted
__device__ int   g_eid[NE];              // original edge id, dst-sorted
__device__ float g_eattr[NE * ED];       // edge_attr rows in dst-sorted order

// ---------------------------------------------------------------------------
// Detect int64 vs int32 edge_idx (one warp, ballot)
// ---------------------------------------------------------------------------
__global__ void detect_idx_kernel(const long long* __restrict__ idx) {
    int lane = threadIdx.x;
    long long v = idx[lane];
    int bad = (v < 0 || v >= (long long)NN) ? 1 : 0;
    unsigned m = __ballot_sync(0xffffffffu, bad);
    if (lane == 0) g_idx64 = (m == 0u);
}

// ---------------------------------------------------------------------------
// CSR build
// ---------------------------------------------------------------------------
__global__ void zero_cnt_kernel() {
    int i = blockIdx.x * blockDim.x + threadIdx.x;
    if (i < NN) g_cnt[i] = 0;
}

__global__ void hist_kernel(const void* __restrict__ edge_idx) {
    int e = blockIdx.x * blockDim.x + threadIdx.x;
    if (e >= NE) return;
    int dst;
    if (g_idx64) dst = (int)((const long long*)edge_idx)[NE + e];
    else         dst = ((const int*)edge_idx)[NE + e];
    atomicAdd(&g_cnt[dst], 1);
}

__global__ void local_scan_kernel() {
    __shared__ int sdata[1024];
    int i = blockIdx.x * 1024 + threadIdx.x;
    int v = (i < NN) ? g_cnt[i] : 0;
    sdata[threadIdx.x] = v;
    __syncthreads();
    #pragma unroll
    for (int off = 1; off < 1024; off <<= 1) {
        int t = (threadIdx.x >= off) ? sdata[threadIdx.x - off] : 0;
        __syncthreads();
        sdata[threadIdx.x] += t;
        __syncthreads();
    }
    if (i < NN) g_rowptr[i] = sdata[threadIdx.x] - v;   // local exclusive
    if (threadIdx.x == 1023) g_blocksum[blockIdx.x] = sdata[1023];
}

__global__ void scan_sums_kernel() {
    __shared__ int sd[64];
    int t = threadIdx.x;
    int v = (t < SCAN_NBLK) ? g_blocksum[t] : 0;
    sd[t] = v;
    __syncthreads();
    #pragma unroll
    for (int off = 1; off < 64; off <<= 1) {
        int u = (t >= off) ? sd[t - off] : 0;
        __syncthreads();
        sd[t] += u;
        __syncthreads();
    }
    if (t < SCAN_NBLK) g_blockoff[t] = sd[t] - v;   // exclusive
}

__global__ void add_off_kernel() {
    int i = blockIdx.x * 1024 + threadIdx.x;
    if (i < NN) {
        int v = g_rowptr[i] + g_blockoff[blockIdx.x];
        g_rowptr[i] = v;
        g_cursor[i] = v;
    }
    if (i == 0) g_rowptr[NN] = NE;
}

__global__ void scatter_kernel(const void* __restrict__ edge_idx) {
    int e = blockIdx.x * blockDim.x + threadIdx.x;
    if (e >= NE) return;
    int src, dst;
    if (g_idx64) {
        src = (int)((const long long*)edge_idx)[e];
        dst = (int)((const long long*)edge_idx)[NE + e];
    } else {
        src = ((const int*)edge_idx)[e];
        dst = ((const int*)edge_idx)[NE + e];
    }
    int pos = atomicAdd(&g_cursor[dst], 1);
    g_src[pos] = src;
    g_eid[pos] = e;
}

// Gather edge_attr rows into dst-sorted order (coalesced writes).
__global__ void gather_attr_kernel(const float* __restrict__ edge_attr) {
    int i = blockIdx.x * blockDim.x + threadIdx.x;   // one float4 per thread
    if (i >= NE * 4) return;
    int j = i >> 2, c = i & 3;
    int eid = g_eid[j];
    ((float4*)g_eattr)[(size_t)j * 4 + c] =
        ((const float4*)edge_attr)[(size_t)eid * 4 + c];
}

// ---------------------------------------------------------------------------
// Edge aggregation (CSR, no atomics): one warp per dst node.
// edge_attr is pre-sorted (sequential reads, address independent of any load);
// only x[src] is a gather. Edge loop unrolled by 2: both edges' loads issue
// before the FMA chains -> 2 independent memory chains.
// ---------------------------------------------------------------------------
#define MCHAIN(m, t0, t1, t2, t3)                                              \
    m.x += t0.x*w[0].x;  m.y += t0.x*w[0].y;  m.z += t0.x*w[0].z;  m.w += t0.x*w[0].w;  \
    m.x += t0.y*w[1].x;  m.y += t0.y*w[1].y;  m.z += t0.y*w[1].z;  m.w += t0.y*w[1].w;  \
    m.x += t0.z*w[2].x;  m.y += t0.z*w[2].y;  m.z += t0.z*w[2].z;  m.w += t0.z*w[2].w;  \
    m.x += t0.w*w[3].x;  m.y += t0.w*w[3].y;  m.z += t0.w*w[3].z;  m.w += t0.w*w[3].w;  \
    m.x += t1.x*w[4].x;  m.y += t1.x*w[4].y;  m.z += t1.x*w[4].z;  m.w += t1.x*w[4].w;  \
    m.x += t1.y*w[5].x;  m.y += t1.y*w[5].y;  m.z += t1.y*w[5].z;  m.w += t1.y*w[5].w;  \
    m.x += t1.z*w[6].x;  m.y += t1.z*w[6].y;  m.z += t1.z*w[6].z;  m.w += t1.z*w[6].w;  \
    m.x += t1.w*w[7].x;  m.y += t1.w*w[7].y;  m.z += t1.w*w[7].z;  m.w += t1.w*w[7].w;  \
    m.x += t2.x*w[8].x;  m.y += t2.x*w[8].y;  m.z += t2.x*w[8].z;  m.w += t2.x*w[8].w;  \
    m.x += t2.y*w[9].x;  m.y += t2.y*w[9].y;  m.z += t2.y*w[9].z;  m.w += t2.y*w[9].w;  \
    m.x += t2.z*w[10].x; m.y += t2.z*w[10].y; m.z += t2.z*w[10].z; m.w += t2.z*w[10].w; \
    m.x += t2.w*w[11].x; m.y += t2.w*w[11].y; m.z += t2.w*w[11].z; m.w += t2.w*w[11].w; \
    m.x += t3.x*w[12].x; m.y += t3.x*w[12].y; m.z += t3.x*w[12].z; m.w += t3.x*w[12].w; \
    m.x += t3.y*w[13].x; m.y += t3.y*w[13].y; m.z += t3.y*w[13].z; m.w += t3.y*w[13].w; \
    m.x += t3.z*w[14].x; m.y += t3.z*w[14].y; m.z += t3.z*w[14].z; m.w += t3.z*w[14].w; \
    m.x += t3.w*w[15].x; m.y += t3.w*w[15].y; m.z += t3.w*w[15].z; m.w += t3.w*w[15].w;

__global__ void __launch_bounds__(256)
aggr_kernel(const float* __restrict__ xin,
            const float* __restrict__ We,
            const float* __restrict__ be,
            const float* __restrict__ eps, int l,
            float* __restrict__ aggr) {
    int lane = threadIdx.x & 31;
    int warp = (blockIdx.x * blockDim.x + threadIdx.x) >> 5;
    int nwarps = (gridDim.x * blockDim.x) >> 5;
    int c0 = lane * 4;

    float4 w[ED];
    #pragma unroll
    for (int k = 0; k < ED; k++)
        w[k] = *(const float4*)(We + k * DD + c0);
    float4 bias = *(const float4*)(be + c0);
    float s = 1.0f + eps[l];

    for (int d = warp; d < NN; d += nwarps) {
        float4 xv = *(const float4*)(xin + (size_t)d * DD + c0);
        float4 acc = make_float4(xv.x * s, xv.y * s, xv.z * s, xv.w * s);
        int beg = g_rowptr[d], end = g_rowptr[d + 1];

        int j = beg;
        for (; j + 1 < end; j += 2) {
            int s0 = g_src[j];
            int s1 = g_src[j + 1];
            const float4* p0 = (const float4*)(g_eattr + (size_t)j * ED);
            float4 a0 = p0[0], a1 = p0[1], a2 = p0[2], a3 = p0[3];
            float4 b0 = p0[4], b1 = p0[5], b2 = p0[6], b3 = p0[7];
            float4 xs0 = *(const float4*)(xin + (size_t)s0 * DD + c0);
            float4 xs1 = *(const float4*)(xin + (size_t)s1 * DD + c0);

            float4 m0 = bias;
            MCHAIN(m0, a0, a1, a2, a3)
            float4 m1 = bias;
            MCHAIN(m1, b0, b1, b2, b3)

            acc.x += fmaxf(m0.x + xs0.x, 0.0f) + fmaxf(m1.x + xs1.x, 0.0f);
            acc.y += fmaxf(m0.y + xs0.y, 0.0f) + fmaxf(m1.y + xs1.y, 0.0f);
            acc.z += fmaxf(m0.z + xs0.z, 0.0f) + fmaxf(m1.z + xs1.z, 0.0f);
            acc.w += fmaxf(m0.w + xs0.w, 0.0f) + fmaxf(m1.w + xs1.w, 0.0f);
        }
        if (j < end) {
            int s0 = g_src[j];
            const float4* p0 = (const float4*)(g_eattr + (size_t)j * ED);
            float4 a0 = p0[0], a1 = p0[1], a2 = p0[2], a3 = p0[3];
            float4 xs0 = *(const float4*)(xin + (size_t)s0 * DD + c0);
            float4 m0 = bias;
            MCHAIN(m0, a0, a1, a2, a3)
            acc.x += fmaxf(m0.x + xs0.x, 0.0f);
            acc.y += fmaxf(m0.y + xs0.y, 0.0f);
            acc.z += fmaxf(m0.z + xs0.z, 0.0f);
            acc.w += fmaxf(m0.w + xs0.w, 0.0f);
        }
        *(float4*)(aggr + (size_t)d * DD + c0) = acc;
    }
}

// ---------------------------------------------------------------------------
// Fused node MLP (R2 form): C = gelu_exact(A @ W1 + b1) @ W2 + b2
// 128-row tiles, both weights resident, 8x8 register tiles.
// ---------------------------------------------------------------------------
#define SA_PITCH 132
#define MLP_SMEM_FLOATS (128 * SA_PITCH + 2 * 128 * 128 + 256)
#define MLP_SMEM_BYTES (MLP_SMEM_FLOATS * 4)

__global__ void mlp_kernel(const float* __restrict__ A,
                           const float* __restrict__ W1g,
                           const float* __restrict__ b1g,
                           const float* __restrict__ W2g,
                           const float* __restrict__ b2g,
                           float* __restrict__ C) {
    extern __shared__ float sm[];
    float* sA  = sm;                      // 128 x 132 (padded)
    float* sW1 = sm + 128 * SA_PITCH;     // 128 x 128
    float* sW2 = sW1 + 128 * 128;         // 128 x 128
    float* sb1 = sW2 + 128 * 128;         // 128
    float* sb2 = sb1 + 128;               // 128

    int tid = threadIdx.x;
    int row0 = blockIdx.x * 128;

    for (int i = tid; i < 128 * 32; i += 256) {
        ((float4*)sW1)[i] = ((const float4*)W1g)[i];
        ((float4*)sW2)[i] = ((const float4*)W2g)[i];
    }
    if (tid < 128) { sb1[tid] = b1g[tid]; sb2[tid] = b2g[tid]; }
    for (int i = tid; i < 128 * 32; i += 256) {
        int r = i >> 5, k4 = i & 31;
        int gr = row0 + r;
        float4 v = (gr < NN) ? ((const float4*)(A + (size_t)gr * DD))[k4]
                             : make_float4(0.f, 0.f, 0.f, 0.f);
        *(float4*)(sA + r * SA_PITCH + k4 * 4) = v;
    }
    __syncthreads();

    int tx = tid & 15, ty = tid >> 4;
    int r0 = ty * 8, cc = tx * 8;

    float acc[8][8];
    #pragma unroll
    for (int i = 0; i < 8; i++)
        #pragma unroll
        for (int j = 0; j < 8; j++) acc[i][j] = 0.0f;

    #pragma unroll 4
    for (int k = 0; k < 128; k++) {
        float4 wa = *(const float4*)(sW1 + k * 128 + cc);
        float4 wb = *(const float4*)(sW1 + k * 128 + cc + 4);
        float a[8];
        #pragma unroll
        for (int i = 0; i < 8; i++) a[i] = sA[(r0 + i) * SA_PITCH + k];
        #pragma unroll
        for (int i = 0; i < 8; i++) {
            acc[i][0] += a[i] * wa.x; acc[i][1] += a[i] * wa.y;
            acc[i][2] += a[i] * wa.z; acc[i][3] += a[i] * wa.w;
            acc[i][4] += a[i] * wb.x; acc[i][5] += a[i] * wb.y;
            acc[i][6] += a[i] * wb.z; acc[i][7] += a[i] * wb.w;
        }
    }
    __syncthreads();

    #pragma unroll
    for (int i = 0; i < 8; i++) {
        #pragma unroll
        for (int j = 0; j < 8; j++) {
            float h = acc[i][j] + sb1[cc + j];
            h = 0.5f * h * (1.0f + erff(h * 0.70710678118654752f));
            sA[(r0 + i) * SA_PITCH + cc + j] = h;
            acc[i][j] = 0.0f;
        }
    }
    __syncthreads();

    #pragma unroll 4
    for (int k = 0; k < 128; k++) {
        float4 wa = *(const float4*)(sW2 + k * 128 + cc);
        float4 wb = *(const float4*)(sW2 + k * 128 + cc + 4);
        float a[8];
        #pragma unroll
        for (int i = 0; i < 8; i++) a[i] = sA[(r0 + i) * SA_PITCH + k];
        #pragma unroll
        for (int i = 0; i < 8; i++) {
            acc[i][0] += a[i] * wa.x; acc[i][1] += a[i] * wa.y;
            acc[i][2] += a[i] * wa.z; acc[i][3] += a[i] * wa.w;
            acc[i][4] += a[i] * wb.x; acc[i][5] += a[i] * wb.y;
            acc[i][6] += a[i] * wb.z; acc[i][7] += a[i] * wb.w;
        }
    }

    #pragma unroll
    for (int i = 0; i < 8; i++) {
        int gr = row0 + r0 + i;
        if (gr < NN) {
            float4 o0 = make_float4(acc[i][0] + sb2[cc],     acc[i][1] + sb2[cc + 1],
                                    acc[i][2] + sb2[cc + 2], acc[i][3] + sb2[cc + 3]);
            float4 o1 = make_float4(acc[i][4] + sb2[cc + 4], acc[i][5] + sb2[cc + 5],
                                    acc[i][6] + sb2[cc + 6], acc[i][7] + sb2[cc + 7]);
            *(float4*)(C + (size_t)gr * DD + cc) = o0;
            *(float4*)(C + (size_t)gr * DD + cc + 4) = o1;
        }
    }
}

// ---------------------------------------------------------------------------
// Launch
// ---------------------------------------------------------------------------
extern "C" void kernel_launch(void* const* d_in, const int* in_sizes, int n_in,
                              void* d_out, int out_size) {
    const float* x         = (const float*)d_in[0];
    const float* edge_attr = (const float*)d_in[1];
    const float* W1        = (const float*)d_in[2];
    const float* b1        = (const float*)d_in[3];
    const float* W2        = (const float*)d_in[4];
    const float* b2        = (const float*)d_in[5];
    const float* We        = (const float*)d_in[6];
    const float* be        = (const float*)d_in[7];
    const float* eps       = (const float*)d_in[8];
    const void*  edge_idx  = d_in[9];
    float* out = (float*)d_out;

    float *bufA, *bufB;
    cudaGetSymbolAddress((void**)&bufA, g_bufA);
    cudaGetSymbolAddress((void**)&bufB, g_bufB);

    cudaFuncSetAttribute(mlp_kernel,
                         cudaFuncAttributeMaxDynamicSharedMemorySize,
                         MLP_SMEM_BYTES);

    // ---- CSR build + attr pre-sort (once per launch) ----
    detect_idx_kernel<<<1, 32>>>((const long long*)edge_idx);
    zero_cnt_kernel<<<(NN + 255) / 256, 256>>>();
    hist_kernel<<<(NE + 255) / 256, 256>>>(edge_idx);
    local_scan_kernel<<<SCAN_NBLK, 1024>>>();
    scan_sums_kernel<<<1, 64>>>();
    add_off_kernel<<<SCAN_NBLK, 1024>>>();
    scatter_kernel<<<(NE + 255) / 256, 256>>>(edge_idx);
    gather_attr_kernel<<<(NE * 4 + 255) / 256, 256>>>(edge_attr);

    const int aggr_blocks = (NN * 32 + 255) / 256;   // one warp per node
    const int mlp_blocks  = (NN + 127) / 128;

    const float* xin = x;
    for (int l = 0; l < 3; l++) {
        float* aggr = (l == 1) ? bufB : bufA;
        float* xout = (l == 0) ? bufA : ((l == 1) ? bufB : out);

        aggr_kernel<<<aggr_blocks, 256>>>(xin, We + l * ED * DD,
                                          be + l * DD, eps, l, aggr);
        mlp_kernel<<<mlp_blocks, 256, MLP_SMEM_BYTES>>>(
            aggr, W1 + l * DD * DD, b1 + l * DD,
            W2 + l * DD * DD, b2 + l * DD, xout);
        xin = xout;
    }
}